// round 11
// baseline (speedup 1.0000x reference)
#include <cuda_runtime.h>

// AccRNNCell: B=512, T=512, F=64, U=512, P=32, L=3
// Persistent batch-parallel kernel, 128 CTAs x 4 batch rows, 512 threads.
// R6 shape: 4 k-split groups x 128 col-threads; 4 cols x 4 rows per thread
// (16 MACs/k via 8 FFMA2). Weight loads software-pipelined as two 8-deep
// LDG.128 buffers so each load half is covered by the other half's FMA phase.

#define UU 512
#define FF 64
#define PP 32
#define NL 3
#define BT 4
#define TPB 512
#define NG 4              // k-split groups
#define TT 512
#define BB 512

typedef unsigned long long u64;

// hsT + prevT + nsT + part[NG] + accS + wpart
#define SMEM_FLOATS (NL*UU*BT + UU*BT + UU*BT + NG*UU*BT + BT*PP + TPB)
#define SMEM_BYTES  (SMEM_FLOATS * 4)

__device__ __forceinline__ u64 pack2(float x, float y) {
    u64 v; asm("mov.b64 %0, {%1, %2};" : "=l"(v) : "f"(x), "f"(y)); return v;
}

__device__ __forceinline__ void fma8(const float4* __restrict__ w,
                                     const float* __restrict__ S,  // + k0*BT
                                     u64* __restrict__ a)
{
    #pragma unroll
    for (int i = 0; i < 8; ++i) {
        ulonglong2 h = *reinterpret_cast<const ulonglong2*>(S + i * BT);
        u64 w0 = pack2(w[i].x, w[i].x), w1 = pack2(w[i].y, w[i].y);
        u64 w2 = pack2(w[i].z, w[i].z), w3 = pack2(w[i].w, w[i].w);
        asm("fma.rn.f32x2 %0, %1, %2, %0;" : "+l"(a[0]) : "l"(w0), "l"(h.x));
        asm("fma.rn.f32x2 %0, %1, %2, %0;" : "+l"(a[1]) : "l"(w0), "l"(h.y));
        asm("fma.rn.f32x2 %0, %1, %2, %0;" : "+l"(a[2]) : "l"(w1), "l"(h.x));
        asm("fma.rn.f32x2 %0, %1, %2, %0;" : "+l"(a[3]) : "l"(w1), "l"(h.y));
        asm("fma.rn.f32x2 %0, %1, %2, %0;" : "+l"(a[4]) : "l"(w2), "l"(h.x));
        asm("fma.rn.f32x2 %0, %1, %2, %0;" : "+l"(a[5]) : "l"(w2), "l"(h.y));
        asm("fma.rn.f32x2 %0, %1, %2, %0;" : "+l"(a[6]) : "l"(w3), "l"(h.x));
        asm("fma.rn.f32x2 %0, %1, %2, %0;" : "+l"(a[7]) : "l"(w3), "l"(h.y));
    }
}

__device__ __forceinline__ void load8(float4* __restrict__ w,
                                      const float* __restrict__ W)  // + k*UU (+j0)
{
    #pragma unroll
    for (int i = 0; i < 8; ++i)
        w[i] = __ldg(reinterpret_cast<const float4*>(W + (size_t)i * UU));
}

// a[2c+h] = f32x2 over rows (2h,2h+1) for column j0+c.
// Software-pipelined: wa/wb 8-deep buffers; each half's loads are in flight
// while the other half's FMAs issue. Last 16-k block peeled (no overrun).
template<int K>
__device__ __forceinline__ void gemm_rp(const float* __restrict__ W,   // + kbeg*UU + j0
                                        const float* __restrict__ S,   // + kbeg*BT
                                        u64* __restrict__ a)
{
    static_assert(K % 16 == 0, "K must be multiple of 16");
    float4 wa[8], wb[8];
    load8(wa, W);
    #pragma unroll 2
    for (int k0 = 0; k0 < K - 16; k0 += 16) {
        load8(wb, W + (size_t)(k0 + 8) * UU);
        fma8(wa, S + k0 * BT, a);
        load8(wa, W + (size_t)(k0 + 16) * UU);
        fma8(wb, S + (k0 + 8) * BT, a);
    }
    load8(wb, W + (size_t)(K - 8) * UU);
    fma8(wa, S + (K - 16) * BT, a);
    fma8(wb, S + (K - 8) * BT, a);
}

__device__ __forceinline__ void store_part(float* __restrict__ pp, const u64* __restrict__ a) {
#pragma unroll
    for (int c = 0; c < 4; ++c) {
        ulonglong2 v; v.x = a[2 * c]; v.y = a[2 * c + 1];
        *reinterpret_cast<ulonglong2*>(pp + c * BT) = v;
    }
}

__global__ void __launch_bounds__(TPB, 1) accrnn_persistent(
    const float* __restrict__ x,
    const float* __restrict__ WA,  const float* __restrict__ bA,
    const float* __restrict__ WB0, const float* __restrict__ bB0,
    const float* __restrict__ WBr, const float* __restrict__ bBr,
    const float* __restrict__ WC,  const float* __restrict__ bC,
    const float* __restrict__ Wout, const float* __restrict__ bout,
    float* __restrict__ out)
{
    extern __shared__ float smem[];
    float* hsT   = smem;                       // [NL][UU][BT]
    float* prevT = hsT + NL * UU * BT;         // [UU][BT]
    float* nsT   = prevT + UU * BT;            // [UU][BT]
    float* part  = nsT + UU * BT;              // [NG][UU][BT]
    float* accS  = part + NG * UU * BT;        // [BT*PP]
    float* wpart = accS + BT * PP;             // [TPB]

    const int tid = threadIdx.x;
    const int b0  = blockIdx.x * BT;
    const int grp = tid >> 7;          // 0..3
    const int ct  = tid & 127;
    const int j0  = ct * 4;

    for (int i = tid; i < NL * UU * BT; i += TPB) hsT[i] = 0.f;
    if (tid < BT * PP) accS[tid] = 0.f;
    __syncthreads();

    const int xr = (tid >> 6) & 3;
    const int xf = tid & 63;
    const float* xrow = x + ((size_t)(b0 + xr) * TT) * FF + xf;

    for (int t = 0; t < TT; ++t) {
        // ---- prevT = concat(x_t, acc) ----
        if (tid < BT * FF) prevT[xf * BT + xr] = xrow[(size_t)t * FF];
        if (tid < BT * PP) {
            int r = tid >> 5, p = tid & 31;
            prevT[(FF + p) * BT + r] = accS[tid];
        }
        __syncthreads();

        #pragma unroll
        for (int l = 0; l < NL; ++l) {
            // ---- stage 1: ns = hs[l]@WA[l] (grp0/1) + prev@WB (grp2/3) ----
            u64 a[8];
            if (grp == 0) {
                #pragma unroll
                for (int c = 0; c < 4; ++c) {
                    float b = bA[l * UU + j0 + c] +
                              ((l == 0) ? bB0[j0 + c] : bBr[(l - 1) * UU + j0 + c]);
                    a[2 * c] = a[2 * c + 1] = pack2(b, b);
                }
            } else {
                #pragma unroll
                for (int i = 0; i < 8; ++i) a[i] = 0ull;
            }
            if (grp < 2) {
                const float* Wa = WA + (size_t)l * UU * UU + j0;
                int kbeg = grp * (UU / 2);
                gemm_rp<UU / 2>(Wa + (size_t)kbeg * UU, hsT + l * UU * BT + kbeg * BT, a);
            } else if (l == 0) {
                int kbeg = (grp - 2) * ((FF + PP) / 2);
                gemm_rp<(FF + PP) / 2>(WB0 + j0 + (size_t)kbeg * UU, prevT + kbeg * BT, a);
            } else {
                const float* Wb = WBr + (size_t)(l - 1) * UU * UU + j0;
                int kbeg = (grp - 2) * (UU / 2);
                gemm_rp<UU / 2>(Wb + (size_t)kbeg * UU, prevT + kbeg * BT, a);
            }
            store_part(part + grp * UU * BT + j0 * BT, a);
            __syncthreads();
            {   // combine: 1 col per thread -> nsT and hsT[l]
                int col = tid;
                float4 s = *reinterpret_cast<float4*>(part + col * BT);
                #pragma unroll
                for (int g = 1; g < NG; ++g) {
                    float4 q = *reinterpret_cast<float4*>(part + g * UU * BT + col * BT);
                    s.x += q.x; s.y += q.y; s.z += q.z; s.w += q.w;
                }
                *reinterpret_cast<float4*>(nsT + col * BT) = s;
                *reinterpret_cast<float4*>(hsT + l * UU * BT + col * BT) = s;
            }
            __syncthreads();

            // ---- stage 2: prev' = ns @ WC[l] + bC[l], 4-way k-split ----
            u64 c[8];
            if (grp == 0) {
                #pragma unroll
                for (int cc = 0; cc < 4; ++cc) {
                    float b = bC[l * UU + j0 + cc];
                    c[2 * cc] = c[2 * cc + 1] = pack2(b, b);
                }
            } else {
                #pragma unroll
                for (int i = 0; i < 8; ++i) c[i] = 0ull;
            }
            {
                int kbeg = grp * (UU / NG);
                gemm_rp<UU / NG>(WC + (size_t)l * UU * UU + (size_t)kbeg * UU + j0,
                                 nsT + kbeg * BT, c);
            }
            store_part(part + grp * UU * BT + j0 * BT, c);
            __syncthreads();
            {   // combine -> prevT
                int col = tid;
                float4 s = *reinterpret_cast<float4*>(part + col * BT);
                #pragma unroll
                for (int g = 1; g < NG; ++g) {
                    float4 q = *reinterpret_cast<float4*>(part + g * UU * BT + col * BT);
                    s.x += q.x; s.y += q.y; s.z += q.z; s.w += q.w;
                }
                *reinterpret_cast<float4*>(prevT + col * BT) = s;
            }
            __syncthreads();
        }

        // ---- res = prev @ Wout + bout ; acc += res ; emit ----
        {
            int rp = tid & 127;
            int r = rp >> 5, p = rp & 31;
            float s = (grp == 0) ? bout[p] : 0.f;
            int kbeg = grp * (UU / NG);
            #pragma unroll 8
            for (int k = kbeg; k < kbeg + UU / NG; ++k)
                s = fmaf(prevT[k * BT + r], Wout[k * PP + p], s);
            wpart[tid] = s;
        }
        __syncthreads();
        if (tid < BT * PP) {
            int r = tid >> 5, p = tid & 31;
            float tot = wpart[tid] + wpart[tid + 128] + wpart[tid + 256] + wpart[tid + 384];
            accS[tid] += tot;
            out[((size_t)(b0 + r) * TT + t) * PP + p] = tot;
        }
        __syncthreads();
    }
}

extern "C" void kernel_launch(void* const* d_in, const int* in_sizes, int n_in,
                              void* d_out, int out_size)
{
    const float* x    = (const float*)d_in[0];
    const float* WA   = (const float*)d_in[1];
    const float* bA   = (const float*)d_in[2];
    const float* WB0  = (const float*)d_in[3];
    const float* bB0  = (const float*)d_in[4];
    const float* WBr  = (const float*)d_in[5];
    const float* bBr  = (const float*)d_in[6];
    const float* WC   = (const float*)d_in[7];
    const float* bC   = (const float*)d_in[8];
    const float* Wout = (const float*)d_in[9];
    const float* bout = (const float*)d_in[10];
    float* out = (float*)d_out;

    cudaFuncSetAttribute(accrnn_persistent,
                         cudaFuncAttributeMaxDynamicSharedMemorySize, SMEM_BYTES);
    accrnn_persistent<<<BB / BT, TPB, SMEM_BYTES>>>(x, WA, bA, WB0, bB0, WBr, bBr,
                                                    WC, bC, Wout, bout, out);
}

// round 12
// speedup vs baseline: 1.5497x; 1.5497x over previous
#include <cuda_runtime.h>

// AccRNNCell: B=512, T=512, F=64, U=512, P=32, L=3
// R12: algebraic collapse. Precompute E1=WC0@WBr0, E2=WC1@WBr1, Eout=WC2@Wout
// and folded biases; per-step work drops from 8 UxU GEMMs to 5 + small.
//   ns0 = h0@WA0 + [xt,acc]@WB0 + f0
//   ns1 = h1@WA1 + ns0@E1 + f1
//   ns2 = h2@WA2 + ns1@E2 + f2
//   res = ns2@Eout + fout ; acc += res
// Persistent kernel: 128 CTAs x 4 batch rows, 512 threads, NG=4 k-split,
// 4 cols x 4 rows per thread via FFMA2, double-buffered weight loads.

#define UU 512
#define FF 64
#define PP 32
#define BT 4
#define TPB 512
#define NG 4
#define TT 512
#define BB 512

typedef unsigned long long u64;

__device__ float dE1[UU * UU];
__device__ float dE2[UU * UU];
__device__ float dEout[UU * PP];
__device__ float df0[UU];
__device__ float df1[UU];
__device__ float df2[UU];
__device__ float dfout[PP];

// hsT[3] + inT(96) + nsT + part[NG] + accS + wpart
#define SMEM_FLOATS (3*UU*BT + 96*BT + UU*BT + NG*UU*BT + BT*PP + TPB)
#define SMEM_BYTES  (SMEM_FLOATS * 4)

// ---------------- precompute kernel ----------------
__global__ void __launch_bounds__(512) precompute(
    const float* __restrict__ WBr, const float* __restrict__ bBr,
    const float* __restrict__ WC,  const float* __restrict__ bC,
    const float* __restrict__ Wout, const float* __restrict__ bout,
    const float* __restrict__ bA,  const float* __restrict__ bB0)
{
    const int bid = blockIdx.x, tid = threadIdx.x;
    __shared__ float row[UU];
    if (bid < 2 * UU) {
        // E1 / E2 row r: E[r][j] = sum_m WC[w][r][m] * WBr[w][m][j]
        int w = bid >> 9;
        int r = bid & (UU - 1);
        const float* Wc = WC + (size_t)w * UU * UU + (size_t)r * UU;
        const float* Wb = WBr + (size_t)w * UU * UU;
        float* E = w ? dE2 : dE1;
        row[tid] = Wc[tid];
        __syncthreads();
        float s = 0.f;
        #pragma unroll 8
        for (int m = 0; m < UU; ++m)
            s = fmaf(row[m], Wb[(size_t)m * UU + tid], s);
        E[(size_t)r * UU + tid] = s;
    } else if (bid < 3 * UU) {
        // Eout row r: Eout[r][p] = sum_m WC[2][r][m] * Wout[m][p]
        int r = bid - 2 * UU;
        const float* Wc = WC + (size_t)2 * UU * UU + (size_t)r * UU;
        int kg = tid >> 5, p = tid & 31;
        float s = 0.f;
        #pragma unroll 8
        for (int m = kg * 32; m < kg * 32 + 32; ++m)
            s = fmaf(Wc[m], Wout[m * PP + p], s);
        row[tid] = s;
        __syncthreads();
        if (tid < PP) {
            float t = 0.f;
            #pragma unroll
            for (int g = 0; g < 16; ++g) t += row[g * 32 + tid];
            dEout[r * PP + tid] = t;
        }
    } else if (bid == 3 * UU) {
        df0[tid] = bA[tid] + bB0[tid];
    } else if (bid == 3 * UU + 1) {
        float s = bA[UU + tid] + bBr[tid];
        #pragma unroll 8
        for (int m = 0; m < UU; ++m)
            s = fmaf(bC[m], WBr[(size_t)m * UU + tid], s);
        df1[tid] = s;
    } else if (bid == 3 * UU + 2) {
        float s = bA[2 * UU + tid] + bBr[UU + tid];
        #pragma unroll 8
        for (int m = 0; m < UU; ++m)
            s = fmaf(bC[UU + m], WBr[(size_t)UU * UU + (size_t)m * UU + tid], s);
        df2[tid] = s;
    } else {
        if (tid < PP) {
            float s = bout[tid];
            #pragma unroll 8
            for (int m = 0; m < UU; ++m)
                s = fmaf(bC[2 * UU + m], Wout[m * PP + tid], s);
            dfout[tid] = s;
        }
    }
}

// ---------------- main persistent kernel ----------------
__device__ __forceinline__ u64 pack2(float x, float y) {
    u64 v; asm("mov.b64 %0, {%1, %2};" : "=l"(v) : "f"(x), "f"(y)); return v;
}

__device__ __forceinline__ void fma8(const float4* __restrict__ w,
                                     const float* __restrict__ S, u64* __restrict__ a)
{
    #pragma unroll
    for (int i = 0; i < 8; ++i) {
        ulonglong2 h = *reinterpret_cast<const ulonglong2*>(S + i * BT);
        u64 w0 = pack2(w[i].x, w[i].x), w1 = pack2(w[i].y, w[i].y);
        u64 w2 = pack2(w[i].z, w[i].z), w3 = pack2(w[i].w, w[i].w);
        asm("fma.rn.f32x2 %0, %1, %2, %0;" : "+l"(a[0]) : "l"(w0), "l"(h.x));
        asm("fma.rn.f32x2 %0, %1, %2, %0;" : "+l"(a[1]) : "l"(w0), "l"(h.y));
        asm("fma.rn.f32x2 %0, %1, %2, %0;" : "+l"(a[2]) : "l"(w1), "l"(h.x));
        asm("fma.rn.f32x2 %0, %1, %2, %0;" : "+l"(a[3]) : "l"(w1), "l"(h.y));
        asm("fma.rn.f32x2 %0, %1, %2, %0;" : "+l"(a[4]) : "l"(w2), "l"(h.x));
        asm("fma.rn.f32x2 %0, %1, %2, %0;" : "+l"(a[5]) : "l"(w2), "l"(h.y));
        asm("fma.rn.f32x2 %0, %1, %2, %0;" : "+l"(a[6]) : "l"(w3), "l"(h.x));
        asm("fma.rn.f32x2 %0, %1, %2, %0;" : "+l"(a[7]) : "l"(w3), "l"(h.y));
    }
}

__device__ __forceinline__ void load8(float4* __restrict__ w, const float* __restrict__ W)
{
    #pragma unroll
    for (int i = 0; i < 8; ++i)
        w[i] = __ldg(reinterpret_cast<const float4*>(W + (size_t)i * UU));
}

template<int K>
__device__ __forceinline__ void gemm_rp(const float* __restrict__ W,
                                        const float* __restrict__ S,
                                        u64* __restrict__ a)
{
    static_assert(K % 16 == 0 && K >= 16, "K must be multiple of 16");
    float4 wa[8], wb[8];
    load8(wa, W);
    #pragma unroll 2
    for (int k0 = 0; k0 < K - 16; k0 += 16) {
        load8(wb, W + (size_t)(k0 + 8) * UU);
        fma8(wa, S + k0 * BT, a);
        load8(wa, W + (size_t)(k0 + 16) * UU);
        fma8(wb, S + (k0 + 8) * BT, a);
    }
    load8(wb, W + (size_t)(K - 8) * UU);
    fma8(wa, S + (K - 16) * BT, a);
    fma8(wb, S + (K - 8) * BT, a);
}

__device__ __forceinline__ void store_part(float* __restrict__ pp, const u64* __restrict__ a) {
#pragma unroll
    for (int c = 0; c < 4; ++c) {
        ulonglong2 v; v.x = a[2 * c]; v.y = a[2 * c + 1];
        *reinterpret_cast<ulonglong2*>(pp + c * BT) = v;
    }
}

__global__ void __launch_bounds__(TPB, 1) accrnn_persistent(
    const float* __restrict__ x,
    const float* __restrict__ WA,
    const float* __restrict__ WB0,
    float* __restrict__ out)
{
    extern __shared__ float smem[];
    float* hsT  = smem;                        // [3][UU][BT]
    float* inT  = hsT + 3 * UU * BT;           // [96][BT]
    float* nsT  = inT + 96 * BT;               // [UU][BT]
    float* part = nsT + UU * BT;               // [NG][UU][BT]
    float* accS = part + NG * UU * BT;         // [BT*PP]
    float* wpart = accS + BT * PP;             // [TPB]

    const int tid = threadIdx.x;
    const int b0  = blockIdx.x * BT;
    const int grp = tid >> 7;          // 0..3
    const int ct  = tid & 127;
    const int j0  = ct * 4;

    for (int i = tid; i < 3 * UU * BT; i += TPB) hsT[i] = 0.f;
    if (tid < BT * PP) accS[tid] = 0.f;
    __syncthreads();

    const int xr = (tid >> 6) & 3;
    const int xf = tid & 63;
    const float* xrow = x + ((size_t)(b0 + xr) * TT) * FF + xf;

    for (int t = 0; t < TT; ++t) {
        // ---- inT = concat(x_t, acc), transposed ----
        if (tid < BT * FF) inT[xf * BT + xr] = xrow[(size_t)t * FF];
        if (tid < BT * PP) {
            int r = tid >> 5, p = tid & 31;
            inT[(FF + p) * BT + r] = accS[tid];
        }
        __syncthreads();

        // ======== stage 0: ns0 = h0@WA0 + in@WB0 + f0 ========
        {
            u64 a[8];
            if (grp == 0) {
                #pragma unroll
                for (int c = 0; c < 4; ++c) {
                    float b = df0[j0 + c];
                    a[2 * c] = a[2 * c + 1] = pack2(b, b);
                }
            } else {
                #pragma unroll
                for (int i = 0; i < 8; ++i) a[i] = 0ull;
            }
            if (grp < 3) {
                int kbeg = grp * 160;
                gemm_rp<160>(WA + (size_t)kbeg * UU + j0, hsT + kbeg * BT, a);
            } else {
                gemm_rp<32>(WA + (size_t)480 * UU + j0, hsT + 480 * BT, a);
                gemm_rp<96>(WB0 + j0, inT, a);
            }
            store_part(part + grp * UU * BT + j0 * BT, a);
        }
        __syncthreads();
        {   // combine -> nsT & hsT[0]
            int col = tid;
            float4 s = *reinterpret_cast<float4*>(part + col * BT);
            #pragma unroll
            for (int g = 1; g < NG; ++g) {
                float4 q = *reinterpret_cast<float4*>(part + g * UU * BT + col * BT);
                s.x += q.x; s.y += q.y; s.z += q.z; s.w += q.w;
            }
            *reinterpret_cast<float4*>(nsT + col * BT) = s;
            *reinterpret_cast<float4*>(hsT + col * BT) = s;
        }
        __syncthreads();

        // ======== stages 1,2: ns_s = h_s@WA_s + ns@E_s + f_s ========
        #pragma unroll
        for (int s = 1; s <= 2; ++s) {
            const float* Was = WA + (size_t)s * UU * UU;
            const float* E   = (s == 1) ? dE1 : dE2;
            const float* f   = (s == 1) ? df1 : df2;
            u64 a[8];
            if (grp == 0) {
                #pragma unroll
                for (int c = 0; c < 4; ++c) {
                    float b = f[j0 + c];
                    a[2 * c] = a[2 * c + 1] = pack2(b, b);
                }
            } else {
                #pragma unroll
                for (int i = 0; i < 8; ++i) a[i] = 0ull;
            }
            if (grp < 2) {
                int kbeg = grp * 256;
                gemm_rp<256>(Was + (size_t)kbeg * UU + j0,
                             hsT + s * UU * BT + kbeg * BT, a);
            } else {
                int kbeg = (grp - 2) * 256;
                gemm_rp<256>(E + (size_t)kbeg * UU + j0, nsT + kbeg * BT, a);
            }
            store_part(part + grp * UU * BT + j0 * BT, a);
            __syncthreads();
            {   // combine -> nsT & hsT[s]
                int col = tid;
                float4 sv = *reinterpret_cast<float4*>(part + col * BT);
                #pragma unroll
                for (int g = 1; g < NG; ++g) {
                    float4 q = *reinterpret_cast<float4*>(part + g * UU * BT + col * BT);
                    sv.x += q.x; sv.y += q.y; sv.z += q.z; sv.w += q.w;
                }
                *reinterpret_cast<float4*>(nsT + col * BT) = sv;
                *reinterpret_cast<float4*>(hsT + s * UU * BT + col * BT) = sv;
            }
            __syncthreads();
        }

        // ======== out: res = ns2 @ Eout + fout ; acc += res ========
        {
            int rp = tid & 127;
            int r = rp >> 5, p = rp & 31;
            float s = (grp == 0) ? dfout[p] : 0.f;
            int kbeg = grp * (UU / NG);
            #pragma unroll 8
            for (int k = kbeg; k < kbeg + UU / NG; ++k)
                s = fmaf(nsT[k * BT + r], dEout[k * PP + p], s);
            wpart[tid] = s;
        }
        __syncthreads();
        if (tid < BT * PP) {
            int r = tid >> 5, p = tid & 31;
            float tot = wpart[tid] + wpart[tid + 128] + wpart[tid + 256] + wpart[tid + 384];
            accS[tid] += tot;
            out[((size_t)(b0 + r) * TT + t) * PP + p] = tot;
        }
        __syncthreads();
    }
}

extern "C" void kernel_launch(void* const* d_in, const int* in_sizes, int n_in,
                              void* d_out, int out_size)
{
    const float* x    = (const float*)d_in[0];
    const float* WA   = (const float*)d_in[1];
    const float* bA   = (const float*)d_in[2];
    const float* WB0  = (const float*)d_in[3];
    const float* bB0  = (const float*)d_in[4];
    const float* WBr  = (const float*)d_in[5];
    const float* bBr  = (const float*)d_in[6];
    const float* WC   = (const float*)d_in[7];
    const float* bC   = (const float*)d_in[8];
    const float* Wout = (const float*)d_in[9];
    const float* bout = (const float*)d_in[10];
    float* out = (float*)d_out;

    precompute<<<3 * UU + 4, 512>>>(WBr, bBr, WC, bC, Wout, bout, bA, bB0);

    cudaFuncSetAttribute(accrnn_persistent,
                         cudaFuncAttributeMaxDynamicSharedMemorySize, SMEM_BYTES);
    accrnn_persistent<<<BB / BT, TPB, SMEM_BYTES>>>(x, WA, WB0, out);
}